// round 1
// baseline (speedup 1.0000x reference)
#include <cuda_runtime.h>
#include <cstdint>

#define NPTS 16384
#define NDIM 64
#define NB   8
#define EPSF 0.1f
#define MINS 5
#define NCMAX 512

// ---------------- global scratch (no allocations allowed) ----------------
__device__ float g_xt[(size_t)NB * NDIM * NPTS];   // transposed features (B,D,N)
__device__ short g_lab[(size_t)NB * NDIM * NPTS];  // per-dim local labels (-1 noise)
__device__ int   g_ncl[NB * NDIM];                 // clusters per (b,d)
__device__ int   g_off[NB * NDIM];                 // exclusive prefix per batch

// ---------------- kernel 0: transpose (B,N,D) -> (B,D,N) ----------------
__global__ void transpose_kernel(const float* __restrict__ f) {
    __shared__ float tile[64][65];
    int b  = blockIdx.x >> 8;          // 8 batches
    int n0 = (blockIdx.x & 255) << 6;  // 256 tiles of 64 rows
    int tid = threadIdx.x;
    const float* src = f + ((size_t)b * NPTS + n0) * NDIM;
    #pragma unroll
    for (int idx = tid; idx < 64 * 64; idx += 256) {
        int n = idx >> 6, d = idx & 63;
        tile[n][d] = src[idx];
    }
    __syncthreads();
    #pragma unroll
    for (int idx = tid; idx < 64 * 64; idx += 256) {
        int d = idx >> 6, n = idx & 63;
        g_xt[(((size_t)b * NDIM + d) << 14) + n0 + n] = tile[n][d];
    }
}

// ---------------- block scan helpers (1024 threads = 32 warps) ----------------
__device__ __forceinline__ int blkscan_excl_add(int v, int* aux) {
    int lane = threadIdx.x & 31, wid = threadIdx.x >> 5;
    int incl = v;
    #pragma unroll
    for (int o = 1; o < 32; o <<= 1) {
        int u = __shfl_up_sync(0xffffffffu, incl, o);
        if (lane >= o) incl += u;
    }
    if (lane == 31) aux[wid] = incl;
    __syncthreads();
    if (wid == 0) {
        int w = aux[lane];
        #pragma unroll
        for (int o = 1; o < 32; o <<= 1) {
            int u = __shfl_up_sync(0xffffffffu, w, o);
            if (lane >= o) w += u;
        }
        aux[lane] = w;
    }
    __syncthreads();
    int wex = __shfl_up_sync(0xffffffffu, incl, 1);
    if (lane == 0) wex = 0;
    int pre = (wid > 0) ? (wex + aux[wid - 1]) : wex;
    __syncthreads();
    return pre;
}

__device__ __forceinline__ int blkscan_excl_max(int v, int* aux) {
    int lane = threadIdx.x & 31, wid = threadIdx.x >> 5;
    int incl = v;
    #pragma unroll
    for (int o = 1; o < 32; o <<= 1) {
        int u = __shfl_up_sync(0xffffffffu, incl, o);
        if (lane >= o) incl = max(incl, u);
    }
    if (lane == 31) aux[wid] = incl;
    __syncthreads();
    if (wid == 0) {
        int w = aux[lane];
        #pragma unroll
        for (int o = 1; o < 32; o <<= 1) {
            int u = __shfl_up_sync(0xffffffffu, w, o);
            if (lane >= o) w = max(w, u);
        }
        aux[lane] = w;
    }
    __syncthreads();
    int wex = __shfl_up_sync(0xffffffffu, incl, 1);
    if (lane == 0) wex = -1;
    int pre = (wid > 0) ? max(wex, aux[wid - 1]) : wex;
    __syncthreads();
    return pre;
}

// suffix (reverse) exclusive min: returns min over threads with HIGHER tid
__device__ __forceinline__ int blkscan_excl_min_suffix(int v, int* aux) {
    int lane = threadIdx.x & 31, wid = threadIdx.x >> 5;
    int incl = v;
    #pragma unroll
    for (int o = 1; o < 32; o <<= 1) {
        int u = __shfl_down_sync(0xffffffffu, incl, o);
        if (lane < 32 - o) incl = min(incl, u);
    }
    if (lane == 0) aux[wid] = incl;
    __syncthreads();
    if (wid == 0) {
        int w = aux[lane];
        #pragma unroll
        for (int o = 1; o < 32; o <<= 1) {
            int u = __shfl_down_sync(0xffffffffu, w, o);
            if (lane < 32 - o) w = min(w, u);
        }
        aux[lane] = w;
    }
    __syncthreads();
    int wex = __shfl_down_sync(0xffffffffu, incl, 1);
    if (lane == 31) wex = NPTS;
    int pre = (wid < 31) ? min(wex, aux[wid + 1]) : wex;
    __syncthreads();
    return pre;
}

// ---------------- kernel 1: per-(b,d) 1D DBSCAN ----------------
// smem layout (dynamic):
//   [0,131072)       uint64 sort buffer   (reused after sort)
//   [0,65536)        float  xs[16384]
//   [65536,98304)    u16    ord[16384]
//   [98304,131072)   s16    lastc[16384]
//   [131072,163840)  s16    nextc[16384]
//   [163840,196608)  s16    cid[16384]
//   [196608,212992)  u8     core[16384]
//   [212992,213120)  int    aux[32]
#define SMEM_BYTES 213120

extern __shared__ unsigned char dsm[];

__global__ void __launch_bounds__(1024, 1) dbscan_kernel() {
    uint64_t*       sortb = (uint64_t*)dsm;
    float*          xs    = (float*)dsm;
    unsigned short* ordv  = (unsigned short*)(dsm + 65536);
    short*          lastc = (short*)(dsm + 98304);
    short*          nextc = (short*)(dsm + 131072);
    short*          cidv  = (short*)(dsm + 163840);
    unsigned char*  corev = (unsigned char*)(dsm + 196608);
    int*            aux   = (int*)(dsm + 212992);

    int bd  = blockIdx.x;
    int tid = threadIdx.x;
    const float* x = g_xt + ((size_t)bd << 14);

    // phase 0: build sortable keys  (order-preserving float->uint transform)
    for (int i = tid; i < NPTS; i += 1024) {
        unsigned u = __float_as_uint(x[i]);
        unsigned s = (u & 0x80000000u) ? ~u : (u | 0x80000000u);
        sortb[i] = ((uint64_t)s << 32) | (unsigned)i;
    }
    __syncthreads();

    // phase 1: bitonic sort of 16384 uint64 keys in smem
    for (int k = 2; k <= NPTS; k <<= 1) {
        for (int j = k >> 1; j > 0; j >>= 1) {
            #pragma unroll
            for (int pp = 0; pp < NPTS / 2 / 1024; pp++) {
                int p = tid + pp * 1024;
                int i = ((p & ~(j - 1)) << 1) | (p & (j - 1));
                int l = i | j;
                uint64_t a = sortb[i], b2 = sortb[l];
                uint64_t lo_ = a < b2 ? a : b2;
                uint64_t hi_ = a < b2 ? b2 : a;
                bool asc = (i & k) == 0;
                sortb[i] = asc ? lo_ : hi_;
                sortb[l] = asc ? hi_ : lo_;
            }
            __syncthreads();
        }
    }

    // phase 2: extract xs / ord (overlapping regions -> stage through registers)
    int base = tid << 4;
    uint64_t w[16];
    #pragma unroll
    for (int q = 0; q < 16; q++) w[q] = sortb[base + q];
    __syncthreads();
    #pragma unroll
    for (int q = 0; q < 16; q++) {
        unsigned s = (unsigned)(w[q] >> 32);
        unsigned u = (s & 0x80000000u) ? (s & 0x7fffffffu) : ~s;
        xs[base + q]   = __uint_as_float(u);
        ordv[base + q] = (unsigned short)(w[q] & 0xffffu);
    }
    __syncthreads();

    // phase 3: core test via binary searches (exact searchsorted semantics)
    #pragma unroll
    for (int q = 0; q < 16; q++) {
        int i = base + q;
        float v  = xs[i];
        float tU = v + EPSF;   // right side: count xs[j] <= tU
        float tL = v - EPSF;   // left side:  count xs[j] <  tL
        int lo = 0, hi = NPTS;
        while (lo < hi) { int m = (lo + hi) >> 1; if (xs[m] <= tU) lo = m + 1; else hi = m; }
        int cntHi = lo;
        lo = 0; hi = NPTS;
        while (lo < hi) { int m = (lo + hi) >> 1; if (xs[m] <  tL) lo = m + 1; else hi = m; }
        int cntLo = lo;
        corev[i] = (unsigned char)((cntHi - cntLo) >= MINS);
    }
    __syncthreads();

    // phase 4 (S1): forward inclusive max of (core ? i : -1) -> nearest left core
    {
        int run = -1;
        #pragma unroll
        for (int q = 0; q < 16; q++) {
            int i = base + q;
            int v = corev[i] ? i : -1;
            if (v > run) run = v;
            lastc[i] = (short)run;             // chunk-local inclusive
        }
        int pre = blkscan_excl_max(run, aux);
        #pragma unroll
        for (int q = 0; q < 16; q++) {
            int i = base + q;
            int c = (int)lastc[i];
            if (pre > c) lastc[i] = (short)pre;
        }
    }
    __syncthreads();

    // phase 5 (S2): new_cluster + cumsum -> cid
    {
        int run = 0;
        int tmp[16];
        #pragma unroll
        for (int q = 0; q < 16; q++) {
            int i = base + q;
            int p = (i == 0) ? -1 : (int)lastc[i - 1];   // nearest core strictly left
            float pv = (p >= 0) ? xs[p] : -INFINITY;
            int nc = (corev[i] && ((xs[i] - pv) > EPSF)) ? 1 : 0;
            run += nc;
            tmp[q] = run;                                 // chunk-local inclusive
        }
        int pre = blkscan_excl_add(run, aux);
        #pragma unroll
        for (int q = 0; q < 16; q++) cidv[base + q] = (short)(tmp[q] + pre - 1);
    }
    __syncthreads();

    // phase 6 (S3): backward inclusive min of (core ? i : NPTS) -> nearest right core
    {
        int run = NPTS;
        int tmp[16];
        #pragma unroll
        for (int q = 15; q >= 0; q--) {
            int i = base + q;
            int v = corev[i] ? i : NPTS;
            if (v < run) run = v;
            tmp[q] = run;                                 // chunk-local suffix inclusive
        }
        int pre = blkscan_excl_min_suffix(run, aux);
        #pragma unroll
        for (int q = 0; q < 16; q++) {
            int i = base + q;
            int v = tmp[q];
            nextc[i] = (short)(pre < v ? pre : v);
        }
    }
    __syncthreads();

    // phase 7: labels (sorted domain) -> unsort to g_lab; write ncl
    #pragma unroll
    for (int q = 0; q < 16; q++) {
        int i = base + q;
        int lab;
        if (corev[i]) {
            lab = (int)cidv[i];
        } else {
            int lc = (int)lastc[i], rc = (int)nextc[i];
            float lv = (lc >= 0)   ? xs[lc] : -INFINITY;
            float rv = (rc < NPTS) ? xs[rc] :  INFINITY;
            float dl = xs[i] - lv;
            float dr = rv - xs[i];
            float mn = dl < dr ? dl : dr;
            if (mn <= EPSF) lab = (dl <= dr) ? (int)cidv[lc] : (int)cidv[rc];
            else            lab = -1;
        }
        g_lab[((size_t)bd << 14) + ordv[i]] = (short)lab;
        if (i == NPTS - 1) g_ncl[bd] = (int)cidv[i] + 1;
    }
}

// ---------------- kernel 2: per-batch exclusive prefix of ncl over dims ----------------
__global__ void offsets_kernel() {
    __shared__ int s[NB * NDIM];
    int t = threadIdx.x;
    s[t] = g_ncl[t];
    __syncthreads();
    int b = t >> 6, d = t & 63;
    int off = 0;
    for (int j = 0; j < d; j++) off += s[(b << 6) + j];
    g_off[t] = off;
}

// ---------------- kernel 3: zero + scatter incidence ----------------
__global__ void scatter_kernel(float* __restrict__ out) {
    __shared__ short labs[64 * 128];   // [d][n]
    __shared__ int   offs[64];
    int b  = blockIdx.x >> 7;          // 8 batches
    int n0 = (blockIdx.x & 127) << 7;  // 128 tiles of 128 rows
    int tid = threadIdx.x;
    if (tid < 64) offs[tid] = g_off[(b << 6) + tid];
    for (int idx = tid; idx < 64 * 128; idx += 256) {
        int d = idx >> 7, n = idx & 127;
        labs[idx] = g_lab[(((size_t)(b * NDIM + d)) << 14) + n0 + n];
    }
    __syncthreads();
    float* o = out + (((size_t)b * NPTS) + n0) * NCMAX;
    float4* o4 = (float4*)o;
    float4 z = make_float4(0.f, 0.f, 0.f, 0.f);
    for (int idx = tid; idx < 128 * NCMAX / 4; idx += 256) o4[idx] = z;
    __syncthreads();
    for (int idx = tid; idx < 128 * 64; idx += 256) {
        int n = idx >> 6, d = idx & 63;
        int lab = (int)labs[d * 128 + n];
        if (lab >= 0) {
            int g = lab + offs[d];
            if (g < NCMAX) o[(size_t)n * NCMAX + g] = 1.0f;
        }
    }
}

// ---------------- entry point ----------------
extern "C" void kernel_launch(void* const* d_in, const int* in_sizes, int n_in,
                              void* d_out, int out_size) {
    (void)in_sizes; (void)n_in; (void)out_size;
    const float* f = (const float*)d_in[0];

    cudaFuncSetAttribute(dbscan_kernel,
                         cudaFuncAttributeMaxDynamicSharedMemorySize, SMEM_BYTES);

    transpose_kernel<<<NB * (NPTS / 64), 256>>>(f);
    dbscan_kernel<<<NB * NDIM, 1024, SMEM_BYTES>>>();
    offsets_kernel<<<1, NB * NDIM>>>();
    scatter_kernel<<<NB * (NPTS / 128), 256>>>((float*)d_out);
}

// round 2
// speedup vs baseline: 1.4743x; 1.4743x over previous
#include <cuda_runtime.h>
#include <cstdint>

#define NPTS 16384
#define NDIM 64
#define NB   8
#define EPSF 0.1f
#define MINS 5
#define NCMAX 512
#define FULLM 0xffffffffu

// ---------------- global scratch (no allocations allowed) ----------------
__device__ float g_xt[(size_t)NB * NDIM * NPTS];   // transposed features (B,D,N)
__device__ short g_lab[(size_t)NB * NDIM * NPTS];  // per-dim local labels (-1 noise)
__device__ int   g_ncl[NB * NDIM];                 // clusters per (b,d)
__device__ int   g_off[NB * NDIM];                 // exclusive prefix per batch

extern __shared__ unsigned char dsm[];

// ---------------- kernel 0: transpose (B,N,D) -> (B,D,N) ----------------
__global__ void transpose_kernel(const float* __restrict__ f) {
    __shared__ float tile[64][65];
    int b  = blockIdx.x >> 8;          // 8 batches
    int n0 = (blockIdx.x & 255) << 6;  // 256 tiles of 64 rows
    int tid = threadIdx.x;
    const float* src = f + ((size_t)b * NPTS + n0) * NDIM;
    #pragma unroll
    for (int idx = tid; idx < 64 * 64; idx += 256) {
        int n = idx >> 6, d = idx & 63;
        tile[n][d] = src[idx];
    }
    __syncthreads();
    #pragma unroll
    for (int idx = tid; idx < 64 * 64; idx += 256) {
        int d = idx >> 6, n = idx & 63;
        g_xt[(((size_t)b * NDIM + d) << 14) + n0 + n] = tile[n][d];
    }
}

// ---------------- block scan helpers (1024 threads = 32 warps) ----------------
__device__ __forceinline__ int blkscan_excl_add(int v, int* aux) {
    int lane = threadIdx.x & 31, wid = threadIdx.x >> 5;
    int incl = v;
    #pragma unroll
    for (int o = 1; o < 32; o <<= 1) {
        int u = __shfl_up_sync(FULLM, incl, o);
        if (lane >= o) incl += u;
    }
    if (lane == 31) aux[wid] = incl;
    __syncthreads();
    if (wid == 0) {
        int w = aux[lane];
        #pragma unroll
        for (int o = 1; o < 32; o <<= 1) {
            int u = __shfl_up_sync(FULLM, w, o);
            if (lane >= o) w += u;
        }
        aux[lane] = w;
    }
    __syncthreads();
    int wex = __shfl_up_sync(FULLM, incl, 1);
    if (lane == 0) wex = 0;
    int pre = (wid > 0) ? (wex + aux[wid - 1]) : wex;
    __syncthreads();
    return pre;
}

__device__ __forceinline__ int blkscan_excl_max(int v, int* aux) {
    int lane = threadIdx.x & 31, wid = threadIdx.x >> 5;
    int incl = v;
    #pragma unroll
    for (int o = 1; o < 32; o <<= 1) {
        int u = __shfl_up_sync(FULLM, incl, o);
        if (lane >= o) incl = max(incl, u);
    }
    if (lane == 31) aux[wid] = incl;
    __syncthreads();
    if (wid == 0) {
        int w = aux[lane];
        #pragma unroll
        for (int o = 1; o < 32; o <<= 1) {
            int u = __shfl_up_sync(FULLM, w, o);
            if (lane >= o) w = max(w, u);
        }
        aux[lane] = w;
    }
    __syncthreads();
    int wex = __shfl_up_sync(FULLM, incl, 1);
    if (lane == 0) wex = -1;
    int pre = (wid > 0) ? max(wex, aux[wid - 1]) : wex;
    __syncthreads();
    return pre;
}

// suffix (reverse) exclusive min over HIGHER tids
__device__ __forceinline__ int blkscan_excl_min_suffix(int v, int* aux) {
    int lane = threadIdx.x & 31, wid = threadIdx.x >> 5;
    int incl = v;
    #pragma unroll
    for (int o = 1; o < 32; o <<= 1) {
        int u = __shfl_down_sync(FULLM, incl, o);
        if (lane < 32 - o) incl = min(incl, u);
    }
    if (lane == 0) aux[wid] = incl;
    __syncthreads();
    if (wid == 0) {
        int w = aux[lane];
        #pragma unroll
        for (int o = 1; o < 32; o <<= 1) {
            int u = __shfl_down_sync(FULLM, w, o);
            if (lane < 32 - o) w = min(w, u);
        }
        aux[lane] = w;
    }
    __syncthreads();
    int wex = __shfl_down_sync(FULLM, incl, 1);
    if (lane == 31) wex = NPTS;
    int pre = (wid < 31) ? min(wex, aux[wid + 1]) : wex;
    __syncthreads();
    return pre;
}

// ---------------- kernel 1: per-(b,d) 1D DBSCAN (radix-sort based) ----------------
// dynamic smem layout (bytes):
//   [0,      65536)  u32 k0  -> later float xs[16384]
//   [65536,  98304)  u16 p0  -> ord[16384]
//   [98304, 163840)  u32 k1  -> later s16 lastc @98304, s16 nextc @131072
//   [163840,196608)  u16 p1  -> later s16 cid
//   [196608,229376)  int whist[32][256] -> later u8 core[16384]
//   [229376,230400)  int bintot[256]
//   [230400,230528)  int aux[32]
#define SMEM_BYTES 230528

__global__ void __launch_bounds__(1024, 1) dbscan_kernel() {
    uint32_t*       k0    = (uint32_t*)dsm;
    uint16_t*       p0    = (uint16_t*)(dsm + 65536);
    uint32_t*       k1    = (uint32_t*)(dsm + 98304);
    uint16_t*       p1    = (uint16_t*)(dsm + 163840);
    int*            whist = (int*)(dsm + 196608);
    int*            bintot= (int*)(dsm + 229376);
    int*            aux   = (int*)(dsm + 230400);

    float*          xs    = (float*)dsm;
    uint16_t*       ordv  = p0;
    short*          lastc = (short*)(dsm + 98304);
    short*          nextc = (short*)(dsm + 131072);
    short*          cidv  = (short*)(dsm + 163840);
    unsigned char*  corev = (unsigned char*)(dsm + 196608);

    int bd   = blockIdx.x;
    int tid  = threadIdx.x;
    int lane = tid & 31;
    int wid  = tid >> 5;
    unsigned mask_lt = (1u << lane) - 1u;
    const float* x = g_xt + ((size_t)bd << 14);

    // phase 0: order-preserving float->uint keys, payload = index
    for (int i = tid; i < NPTS; i += 1024) {
        unsigned u = __float_as_uint(x[i]);
        unsigned s = (u & 0x80000000u) ? ~u : (u | 0x80000000u);
        k0[i] = s;
        p0[i] = (uint16_t)i;
    }
    __syncthreads();

    // phase 1: 4-pass 8-bit LSD radix sort.
    // item layout per pass: i = wid*512 + q*32 + lane  (warp-major => stable)
    uint32_t* kcur = k0; uint16_t* pcur = p0;
    uint32_t* kalt = k1; uint16_t* palt = p1;
    int ibase = (wid << 9) + lane;
    for (int pass = 0; pass < 4; pass++) {
        int shift = pass << 3;
        // zero per-warp histograms
        for (int j = tid; j < 32 * 256; j += 1024) whist[j] = 0;
        __syncthreads();
        // histogram (match-aggregated smem atomics)
        #pragma unroll
        for (int q = 0; q < 16; q++) {
            unsigned d = (kcur[ibase + (q << 5)] >> shift) & 255u;
            unsigned m = __match_any_sync(FULLM, d);
            if ((m & mask_lt) == 0)
                atomicAdd(&whist[(wid << 8) + d], __popc(m));
        }
        __syncthreads();
        // bin totals
        int v = 0;
        if (tid < 256) {
            int s = 0;
            #pragma unroll 8
            for (int w2 = 0; w2 < 32; w2++) s += whist[(w2 << 8) + tid];
            v = s;
        }
        // exclusive scan over 256 bins (8 active warps)
        int incl = v;
        #pragma unroll
        for (int o = 1; o < 32; o <<= 1) {
            int u = __shfl_up_sync(FULLM, incl, o);
            if (lane >= o) incl += u;
        }
        if (tid < 256 && lane == 31) aux[wid] = incl;
        __syncthreads();
        if (tid == 0) {
            int r = 0;
            #pragma unroll
            for (int w2 = 0; w2 < 8; w2++) { int c = aux[w2]; aux[w2] = r; r += c; }
        }
        __syncthreads();
        if (tid < 256) bintot[tid] = incl - v + aux[wid];
        __syncthreads();
        // per-(warp,bin) bases, warp-major within bin
        if (tid < 256) {
            int run = bintot[tid];
            #pragma unroll 8
            for (int w2 = 0; w2 < 32; w2++) {
                int c = whist[(w2 << 8) + tid];
                whist[(w2 << 8) + tid] = run;
                run += c;
            }
        }
        __syncthreads();
        // stable rank & scatter
        #pragma unroll
        for (int q = 0; q < 16; q++) {
            int i = ibase + (q << 5);
            unsigned k = kcur[i];
            uint16_t pl = pcur[i];
            unsigned d = (k >> shift) & 255u;
            unsigned m = __match_any_sync(FULLM, d);
            int leader = __ffs(m) - 1;
            int myoff = __popc(m & mask_lt);
            int base2 = 0;
            if (myoff == 0) {
                base2 = whist[(wid << 8) + d];
                whist[(wid << 8) + d] = base2 + __popc(m);
            }
            base2 = __shfl_sync(FULLM, base2, leader);
            int dst = base2 + myoff;
            kalt[dst] = k;
            palt[dst] = pl;
            __syncwarp();
        }
        __syncthreads();
        uint32_t* tk = kcur; kcur = kalt; kalt = tk;
        uint16_t* tp = pcur; pcur = palt; palt = tp;
    }
    // after 4 passes sorted data is back in k0/p0

    // phase 2: keys -> float values in place
    for (int i = tid; i < NPTS; i += 1024) {
        unsigned s = k0[i];
        unsigned u = (s & 0x80000000u) ? (s & 0x7fffffffu) : ~s;
        ((uint32_t*)xs)[i] = u;
    }
    __syncthreads();

    // phase 3: core test — 2 binary searches per THREAD + monotone advance
    int base = tid << 4;
    {
        float v0 = xs[base];
        float tU = v0 + EPSF, tL = v0 - EPSF;
        int lo = 0, hi = NPTS;
        while (lo < hi) { int m = (lo + hi) >> 1; if (xs[m] <= tU) lo = m + 1; else hi = m; }
        int phi = lo;
        lo = 0; hi = NPTS;
        while (lo < hi) { int m = (lo + hi) >> 1; if (xs[m] < tL) lo = m + 1; else hi = m; }
        int plo = lo;
        corev[base] = (unsigned char)((phi - plo) >= MINS);
        #pragma unroll 4
        for (int q = 1; q < 16; q++) {
            float v = xs[base + q];
            float u2 = v + EPSF, l2 = v - EPSF;
            while (phi < NPTS && xs[phi] <= u2) phi++;
            while (plo < NPTS && xs[plo] <  l2) plo++;
            corev[base + q] = (unsigned char)((phi - plo) >= MINS);
        }
    }
    __syncthreads();

    // phase 4: forward inclusive max of (core ? i : -1) -> nearest left core
    {
        int run = -1;
        #pragma unroll
        for (int q = 0; q < 16; q++) {
            int i = base + q;
            int v = corev[i] ? i : -1;
            if (v > run) run = v;
            lastc[i] = (short)run;
        }
        int pre = blkscan_excl_max(run, aux);
        #pragma unroll
        for (int q = 0; q < 16; q++) {
            int i = base + q;
            int c = (int)lastc[i];
            if (pre > c) lastc[i] = (short)pre;
        }
    }
    __syncthreads();

    // phase 5: new_cluster + cumsum -> cid
    {
        int run = 0;
        int tmp[16];
        #pragma unroll
        for (int q = 0; q < 16; q++) {
            int i = base + q;
            int p = (i == 0) ? -1 : (int)lastc[i - 1];
            float pv = (p >= 0) ? xs[p] : -INFINITY;
            int nc = (corev[i] && ((xs[i] - pv) > EPSF)) ? 1 : 0;
            run += nc;
            tmp[q] = run;
        }
        int pre = blkscan_excl_add(run, aux);
        #pragma unroll
        for (int q = 0; q < 16; q++) cidv[base + q] = (short)(tmp[q] + pre - 1);
    }
    __syncthreads();

    // phase 6: backward inclusive min of (core ? i : NPTS) -> nearest right core
    {
        int run = NPTS;
        int tmp[16];
        #pragma unroll
        for (int q = 15; q >= 0; q--) {
            int i = base + q;
            int v = corev[i] ? i : NPTS;
            if (v < run) run = v;
            tmp[q] = run;
        }
        int pre = blkscan_excl_min_suffix(run, aux);
        #pragma unroll
        for (int q = 0; q < 16; q++) {
            int i = base + q;
            int v = tmp[q];
            nextc[i] = (short)(pre < v ? pre : v);
        }
    }
    __syncthreads();

    // phase 7: labels -> unsort to g_lab; write ncl
    #pragma unroll
    for (int q = 0; q < 16; q++) {
        int i = base + q;
        int lab;
        if (corev[i]) {
            lab = (int)cidv[i];
        } else {
            int lc = (int)lastc[i], rc = (int)nextc[i];
            float lv = (lc >= 0)   ? xs[lc] : -INFINITY;
            float rv = (rc < NPTS) ? xs[rc] :  INFINITY;
            float dl = xs[i] - lv;
            float dr = rv - xs[i];
            float mn = dl < dr ? dl : dr;
            if (mn <= EPSF) lab = (dl <= dr) ? (int)cidv[lc] : (int)cidv[rc];
            else            lab = -1;
        }
        g_lab[((size_t)bd << 14) + ordv[i]] = (short)lab;
        if (i == NPTS - 1) g_ncl[bd] = (int)cidv[i] + 1;
    }
}

// ---------------- kernel 2: per-batch exclusive prefix of ncl over dims ----------------
__global__ void offsets_kernel() {
    __shared__ int s[NB * NDIM];
    int t = threadIdx.x;
    s[t] = g_ncl[t];
    __syncthreads();
    int b = t >> 6, d = t & 63;
    int off = 0;
    for (int j = 0; j < d; j++) off += s[(b << 6) + j];
    g_off[t] = off;
}

// ---------------- kernel 3: build rows in smem, stream out coalesced ----------------
// dyn smem: rows 32*512 floats (65536) | labs 64*32 shorts @65536 (4096) | offs @69632 (256)
#define SROWS 32
#define SCAT_SMEM 69888
__global__ void scatter_kernel(float* __restrict__ out) {
    float* rows = (float*)dsm;
    short* labs = (short*)(dsm + 65536);
    int*   offs = (int*)(dsm + 69632);
    int tilesPerB = NPTS / SROWS;                 // 512
    int b  = blockIdx.x / tilesPerB;
    int n0 = (blockIdx.x % tilesPerB) * SROWS;
    int tid = threadIdx.x;                        // 256
    if (tid < NDIM) offs[tid] = g_off[(b << 6) + tid];
    for (int idx = tid; idx < NDIM * SROWS; idx += 256) {
        int d = idx / SROWS, n = idx % SROWS;
        labs[idx] = g_lab[(((size_t)(b * NDIM + d)) << 14) + n0 + n];
    }
    float4* r4 = (float4*)rows;
    float4 z = make_float4(0.f, 0.f, 0.f, 0.f);
    for (int idx = tid; idx < SROWS * NCMAX / 4; idx += 256) r4[idx] = z;
    __syncthreads();
    for (int idx = tid; idx < SROWS * NDIM; idx += 256) {
        int n = idx >> 6, d = idx & 63;
        int lab = (int)labs[d * SROWS + n];
        if (lab >= 0) {
            int g = lab + offs[d];
            if (g < NCMAX) rows[n * NCMAX + g] = 1.0f;
        }
    }
    __syncthreads();
    float4* o4 = (float4*)(out + (((size_t)b * NPTS) + n0) * NCMAX);
    for (int idx = tid; idx < SROWS * NCMAX / 4; idx += 256) o4[idx] = r4[idx];
}

// ---------------- entry point ----------------
extern "C" void kernel_launch(void* const* d_in, const int* in_sizes, int n_in,
                              void* d_out, int out_size) {
    (void)in_sizes; (void)n_in; (void)out_size;
    const float* f = (const float*)d_in[0];

    cudaFuncSetAttribute(dbscan_kernel,
                         cudaFuncAttributeMaxDynamicSharedMemorySize, SMEM_BYTES);
    cudaFuncSetAttribute(scatter_kernel,
                         cudaFuncAttributeMaxDynamicSharedMemorySize, SCAT_SMEM);

    transpose_kernel<<<NB * (NPTS / 64), 256>>>(f);
    dbscan_kernel<<<NB * NDIM, 1024, SMEM_BYTES>>>();
    offsets_kernel<<<1, NB * NDIM>>>();
    scatter_kernel<<<NB * (NPTS / SROWS), 256, SCAT_SMEM>>>((float*)d_out);
}

// round 3
// speedup vs baseline: 1.5242x; 1.0339x over previous
#include <cuda_runtime.h>
#include <cstdint>

#define NPTS 16384
#define NDIM 64
#define NB   8
#define EPSF 0.1f
#define MINS 5
#define NCMAX 512
#define FULLM 0xffffffffu

// ---------------- global scratch (no allocations allowed) ----------------
__device__ float g_xt[(size_t)NB * NDIM * NPTS];   // transposed features (B,D,N)
__device__ short g_lab[(size_t)NB * NDIM * NPTS];  // per-dim local labels (-1 noise)
__device__ int   g_ncl[NB * NDIM];                 // clusters per (b,d)
__device__ int   g_off[NB * NDIM];                 // exclusive prefix per batch

extern __shared__ unsigned char dsm[];

// ---------------- kernel 0: transpose (B,N,D) -> (B,D,N) ----------------
__global__ void transpose_kernel(const float* __restrict__ f) {
    __shared__ float tile[64][65];
    int b  = blockIdx.x >> 8;          // 8 batches
    int n0 = (blockIdx.x & 255) << 6;  // 256 tiles of 64 rows
    int tid = threadIdx.x;
    const float* src = f + ((size_t)b * NPTS + n0) * NDIM;
    #pragma unroll
    for (int idx = tid; idx < 64 * 64; idx += 256) {
        int n = idx >> 6, d = idx & 63;
        tile[n][d] = src[idx];
    }
    __syncthreads();
    #pragma unroll
    for (int idx = tid; idx < 64 * 64; idx += 256) {
        int d = idx >> 6, n = idx & 63;
        g_xt[(((size_t)b * NDIM + d) << 14) + n0 + n] = tile[n][d];
    }
}

// ---------------- block scan helpers (1024 threads = 32 warps) ----------------
__device__ __forceinline__ int blkscan_excl_add(int v, int* aux) {
    int lane = threadIdx.x & 31, wid = threadIdx.x >> 5;
    int incl = v;
    #pragma unroll
    for (int o = 1; o < 32; o <<= 1) {
        int u = __shfl_up_sync(FULLM, incl, o);
        if (lane >= o) incl += u;
    }
    if (lane == 31) aux[wid] = incl;
    __syncthreads();
    if (wid == 0) {
        int w = aux[lane];
        #pragma unroll
        for (int o = 1; o < 32; o <<= 1) {
            int u = __shfl_up_sync(FULLM, w, o);
            if (lane >= o) w += u;
        }
        aux[lane] = w;
    }
    __syncthreads();
    int wex = __shfl_up_sync(FULLM, incl, 1);
    if (lane == 0) wex = 0;
    int pre = (wid > 0) ? (wex + aux[wid - 1]) : wex;
    __syncthreads();
    return pre;
}

__device__ __forceinline__ int blkscan_excl_max(int v, int* aux) {
    int lane = threadIdx.x & 31, wid = threadIdx.x >> 5;
    int incl = v;
    #pragma unroll
    for (int o = 1; o < 32; o <<= 1) {
        int u = __shfl_up_sync(FULLM, incl, o);
        if (lane >= o) incl = max(incl, u);
    }
    if (lane == 31) aux[wid] = incl;
    __syncthreads();
    if (wid == 0) {
        int w = aux[lane];
        #pragma unroll
        for (int o = 1; o < 32; o <<= 1) {
            int u = __shfl_up_sync(FULLM, w, o);
            if (lane >= o) w = max(w, u);
        }
        aux[lane] = w;
    }
    __syncthreads();
    int wex = __shfl_up_sync(FULLM, incl, 1);
    if (lane == 0) wex = -1;
    int pre = (wid > 0) ? max(wex, aux[wid - 1]) : wex;
    __syncthreads();
    return pre;
}

// suffix (reverse) exclusive min over HIGHER tids
__device__ __forceinline__ int blkscan_excl_min_suffix(int v, int* aux) {
    int lane = threadIdx.x & 31, wid = threadIdx.x >> 5;
    int incl = v;
    #pragma unroll
    for (int o = 1; o < 32; o <<= 1) {
        int u = __shfl_down_sync(FULLM, incl, o);
        if (lane < 32 - o) incl = min(incl, u);
    }
    if (lane == 0) aux[wid] = incl;
    __syncthreads();
    if (wid == 0) {
        int w = aux[lane];
        #pragma unroll
        for (int o = 1; o < 32; o <<= 1) {
            int u = __shfl_down_sync(FULLM, w, o);
            if (lane < 32 - o) w = min(w, u);
        }
        aux[lane] = w;
    }
    __syncthreads();
    int wex = __shfl_down_sync(FULLM, incl, 1);
    if (lane == 31) wex = NPTS;
    int pre = (wid < 31) ? min(wex, aux[wid + 1]) : wex;
    __syncthreads();
    return pre;
}

// ---------------- kernel 1: per-(b,d) 1D DBSCAN (radix-sort based, atomic-free) ----------------
// dynamic smem layout (bytes):
//   [0,      65536)  u32 k0   -> later float xs[16384]
//   [65536,  98304)  u16 p0   -> ord[16384]
//   [98304, 163840)  u32 k1   -> later s16 lastc @98304, s16 nextc @131072
//   [163840,196608)  u16 p1   -> later s16 cid
//   [196608,212992)  u16 wh[32][256]  -> later u8 core[16384]
//   [212992,214016)  i32 bintot[256]
//   [214016,214144)  i32 aux[32]
#define SMEM_BYTES 214144

__global__ void __launch_bounds__(1024, 1) dbscan_kernel() {
    uint32_t*       k0    = (uint32_t*)dsm;
    uint16_t*       p0    = (uint16_t*)(dsm + 65536);
    uint32_t*       k1    = (uint32_t*)(dsm + 98304);
    uint16_t*       p1    = (uint16_t*)(dsm + 163840);
    uint16_t*       wh    = (uint16_t*)(dsm + 196608);
    int*            bintot= (int*)(dsm + 212992);
    int*            aux   = (int*)(dsm + 214016);

    float*          xs    = (float*)dsm;
    uint16_t*       ordv  = p0;
    short*          lastc = (short*)(dsm + 98304);
    short*          nextc = (short*)(dsm + 131072);
    short*          cidv  = (short*)(dsm + 163840);
    unsigned char*  corev = (unsigned char*)(dsm + 196608);

    int bd   = blockIdx.x;
    int tid  = threadIdx.x;
    int lane = tid & 31;
    int wid  = tid >> 5;
    unsigned mask_lt = (1u << lane) - 1u;
    const float* x = g_xt + ((size_t)bd << 14);

    // phase 0: order-preserving float->uint keys, payload = index.
    // warp-chunk layout so gmem reads stay coalesced (warp reads 32 consecutive).
    int ibase = (wid << 9) + lane;
    #pragma unroll
    for (int q = 0; q < 16; q++) {
        int i = ibase + (q << 5);
        unsigned u = __float_as_uint(x[i]);
        unsigned s = (u & 0x80000000u) ? ~u : (u | 0x80000000u);
        k0[i] = s;
        p0[i] = (uint16_t)i;
    }
    __syncthreads();

    // phase 1: 4-pass 8-bit LSD radix sort, atomic-free.
    // item layout: i = wid*512 + q*32 + lane (warp-major => stable)
    uint32_t* kcur = k0; uint16_t* pcur = p0;
    uint32_t* kalt = k1; uint16_t* palt = p1;
    for (int pass = 0; pass < 4; pass++) {
        int shift = pass << 3;
        // zero per-warp u16 histograms (16KB = 4096 words)
        for (int j = tid; j < 4096; j += 1024) ((uint32_t*)wh)[j] = 0;
        __syncthreads();
        // histogram: warp-private rows, leader does plain RMW (race-free within warp)
        #pragma unroll
        for (int q = 0; q < 16; q++) {
            unsigned d = (kcur[ibase + (q << 5)] >> shift) & 255u;
            unsigned m = __match_any_sync(FULLM, d);
            if ((m & mask_lt) == 0) {
                int a = (wid << 8) + d;
                wh[a] = (uint16_t)(wh[a] + __popc(m));
            }
            __syncwarp();
        }
        __syncthreads();
        // bin totals
        int v = 0;
        if (tid < 256) {
            int s = 0;
            #pragma unroll 8
            for (int w2 = 0; w2 < 32; w2++) s += (int)wh[(w2 << 8) + tid];
            v = s;
        }
        // exclusive scan over 256 bins (8 active warps)
        int incl = v;
        #pragma unroll
        for (int o = 1; o < 32; o <<= 1) {
            int u = __shfl_up_sync(FULLM, incl, o);
            if (lane >= o) incl += u;
        }
        if (tid < 256 && lane == 31) aux[wid] = incl;
        __syncthreads();
        if (tid == 0) {
            int r = 0;
            #pragma unroll
            for (int w2 = 0; w2 < 8; w2++) { int c = aux[w2]; aux[w2] = r; r += c; }
        }
        __syncthreads();
        if (tid < 256) bintot[tid] = incl - v + aux[wid];
        __syncthreads();
        // per-(warp,bin) bases, warp-major within bin
        if (tid < 256) {
            int run = bintot[tid];
            #pragma unroll 8
            for (int w2 = 0; w2 < 32; w2++) {
                int c = (int)wh[(w2 << 8) + tid];
                wh[(w2 << 8) + tid] = (uint16_t)run;
                run += c;
            }
        }
        __syncthreads();
        // stable rank & scatter (leader RMW, race-free + syncwarp)
        #pragma unroll
        for (int q = 0; q < 16; q++) {
            int i = ibase + (q << 5);
            unsigned k = kcur[i];
            uint16_t pl = pcur[i];
            unsigned d = (k >> shift) & 255u;
            unsigned m = __match_any_sync(FULLM, d);
            int leader = __ffs(m) - 1;
            int myoff = __popc(m & mask_lt);
            int base2 = 0;
            if (myoff == 0) {
                int a = (wid << 8) + d;
                base2 = (int)wh[a];
                wh[a] = (uint16_t)(base2 + __popc(m));
            }
            base2 = __shfl_sync(FULLM, base2, leader);
            int dst = base2 + myoff;
            kalt[dst] = k;
            palt[dst] = pl;
            __syncwarp();
        }
        __syncthreads();
        uint32_t* tk = kcur; kcur = kalt; kalt = tk;
        uint16_t* tp = pcur; pcur = palt; palt = tp;
    }
    // after 4 passes sorted data is back in k0/p0

    // phase 2: keys -> float values in place
    for (int i = tid; i < NPTS; i += 1024) {
        unsigned s = k0[i];
        unsigned u = (s & 0x80000000u) ? (s & 0x7fffffffu) : ~s;
        ((uint32_t*)xs)[i] = u;
    }
    __syncthreads();

    // phase 3: core test — 2 binary searches per THREAD + monotone advance
    int base = tid << 4;
    {
        float v0 = xs[base];
        float tU = v0 + EPSF, tL = v0 - EPSF;
        int lo = 0, hi = NPTS;
        while (lo < hi) { int m = (lo + hi) >> 1; if (xs[m] <= tU) lo = m + 1; else hi = m; }
        int phi = lo;
        lo = 0; hi = NPTS;
        while (lo < hi) { int m = (lo + hi) >> 1; if (xs[m] < tL) lo = m + 1; else hi = m; }
        int plo = lo;
        corev[base] = (unsigned char)((phi - plo) >= MINS);
        #pragma unroll 4
        for (int q = 1; q < 16; q++) {
            float v = xs[base + q];
            float u2 = v + EPSF, l2 = v - EPSF;
            while (phi < NPTS && xs[phi] <= u2) phi++;
            while (plo < NPTS && xs[plo] <  l2) plo++;
            corev[base + q] = (unsigned char)((phi - plo) >= MINS);
        }
    }
    __syncthreads();

    // phase 4: forward inclusive max of (core ? i : -1) -> nearest left core
    {
        int run = -1;
        #pragma unroll
        for (int q = 0; q < 16; q++) {
            int i = base + q;
            int v = corev[i] ? i : -1;
            if (v > run) run = v;
            lastc[i] = (short)run;
        }
        int pre = blkscan_excl_max(run, aux);
        #pragma unroll
        for (int q = 0; q < 16; q++) {
            int i = base + q;
            int c = (int)lastc[i];
            if (pre > c) lastc[i] = (short)pre;
        }
    }
    __syncthreads();

    // phase 5: new_cluster + cumsum -> cid
    {
        int run = 0;
        int tmp[16];
        #pragma unroll
        for (int q = 0; q < 16; q++) {
            int i = base + q;
            int p = (i == 0) ? -1 : (int)lastc[i - 1];
            float pv = (p >= 0) ? xs[p] : -INFINITY;
            int nc = (corev[i] && ((xs[i] - pv) > EPSF)) ? 1 : 0;
            run += nc;
            tmp[q] = run;
        }
        int pre = blkscan_excl_add(run, aux);
        #pragma unroll
        for (int q = 0; q < 16; q++) cidv[base + q] = (short)(tmp[q] + pre - 1);
    }
    __syncthreads();

    // phase 6: backward inclusive min of (core ? i : NPTS) -> nearest right core
    {
        int run = NPTS;
        int tmp[16];
        #pragma unroll
        for (int q = 15; q >= 0; q--) {
            int i = base + q;
            int v = corev[i] ? i : NPTS;
            if (v < run) run = v;
            tmp[q] = run;
        }
        int pre = blkscan_excl_min_suffix(run, aux);
        #pragma unroll
        for (int q = 0; q < 16; q++) {
            int i = base + q;
            int v = tmp[q];
            nextc[i] = (short)(pre < v ? pre : v);
        }
    }
    __syncthreads();

    // phase 7: labels -> unsort to g_lab; write ncl
    #pragma unroll
    for (int q = 0; q < 16; q++) {
        int i = base + q;
        int lab;
        if (corev[i]) {
            lab = (int)cidv[i];
        } else {
            int lc = (int)lastc[i], rc = (int)nextc[i];
            float lv = (lc >= 0)   ? xs[lc] : -INFINITY;
            float rv = (rc < NPTS) ? xs[rc] :  INFINITY;
            float dl = xs[i] - lv;
            float dr = rv - xs[i];
            float mn = dl < dr ? dl : dr;
            if (mn <= EPSF) lab = (dl <= dr) ? (int)cidv[lc] : (int)cidv[rc];
            else            lab = -1;
        }
        g_lab[((size_t)bd << 14) + ordv[i]] = (short)lab;
        if (i == NPTS - 1) g_ncl[bd] = (int)cidv[i] + 1;
    }
}

// ---------------- kernel 2: per-batch exclusive prefix of ncl over dims ----------------
__global__ void offsets_kernel() {
    __shared__ int s[NB * NDIM];
    int t = threadIdx.x;
    s[t] = g_ncl[t];
    __syncthreads();
    int b = t >> 6, d = t & 63;
    int off = 0;
    for (int j = 0; j < d; j++) off += s[(b << 6) + j];
    g_off[t] = off;
}

// ---------------- kernel 3: fused zero + scatter (round-1 version, 78us) ----------------
__global__ void scatter_kernel(float* __restrict__ out) {
    __shared__ short labs[64 * 128];   // [d][n]
    __shared__ int   offs[64];
    int b  = blockIdx.x >> 7;          // 8 batches
    int n0 = (blockIdx.x & 127) << 7;  // 128 tiles of 128 rows
    int tid = threadIdx.x;
    if (tid < 64) offs[tid] = g_off[(b << 6) + tid];
    for (int idx = tid; idx < 64 * 128; idx += 256) {
        int d = idx >> 7, n = idx & 127;
        labs[idx] = g_lab[(((size_t)(b * NDIM + d)) << 14) + n0 + n];
    }
    __syncthreads();
    float* o = out + (((size_t)b * NPTS) + n0) * NCMAX;
    float4* o4 = (float4*)o;
    float4 z = make_float4(0.f, 0.f, 0.f, 0.f);
    for (int idx = tid; idx < 128 * NCMAX / 4; idx += 256) o4[idx] = z;
    __syncthreads();
    for (int idx = tid; idx < 128 * 64; idx += 256) {
        int n = idx >> 6, d = idx & 63;
        int lab = (int)labs[d * 128 + n];
        if (lab >= 0) {
            int g = lab + offs[d];
            if (g < NCMAX) o[(size_t)n * NCMAX + g] = 1.0f;
        }
    }
}

// ---------------- entry point ----------------
extern "C" void kernel_launch(void* const* d_in, const int* in_sizes, int n_in,
                              void* d_out, int out_size) {
    (void)in_sizes; (void)n_in; (void)out_size;
    const float* f = (const float*)d_in[0];

    cudaFuncSetAttribute(dbscan_kernel,
                         cudaFuncAttributeMaxDynamicSharedMemorySize, SMEM_BYTES);

    transpose_kernel<<<NB * (NPTS / 64), 256>>>(f);
    dbscan_kernel<<<NB * NDIM, 1024, SMEM_BYTES>>>();
    offsets_kernel<<<1, NB * NDIM>>>();
    scatter_kernel<<<NB * (NPTS / 128), 256>>>((float*)d_out);
}